// round 10
// baseline (speedup 1.0000x reference)
#include <cuda_runtime.h>
#include <cuda_fp16.h>
#include <cstdint>

#define NN 50000
#define EE 800000
#define SCAN_BLK ((NN + 1023) / 1024)   // 49

// ---------------- device scratch (no allocations allowed) ----------------
__device__ __align__(16) int    g_outdeg[NN];
__device__ __align__(16) int    g_indeg[NN];
__device__ __align__(16) int    g_cursor[NN];
__device__ __align__(16) int    g_rowptr[NN + 1];
__device__ __align__(16) int    g_esrc[EE];
__device__ __align__(16) int    g_bsum[SCAN_BLK];
__device__ __align__(16) int    g_flag[SCAN_BLK];
__device__ __align__(16) float  g_norm_src[NN];
__device__ __align__(16) float  g_norm_dst[NN];
__device__ __align__(16) __half g_x16[(size_t)NN * 64];
__device__ __align__(16) __half g_agg1[(size_t)NN * 64];
__device__ __align__(16) __half g_h1[(size_t)NN * 128];
__device__ __align__(16) __half g_h2[(size_t)NN * 64];

__device__ __forceinline__ uint32_t f2tf32(float v) {
    uint32_t u;
    asm("cvt.rna.tf32.f32 %0, %1;" : "=r"(u) : "f"(v));
    return u;
}

#define MMA_TF32(c0, c1, c2, c3, a0, a1, a2, a3, b0, b1) \
    asm volatile("mma.sync.aligned.m16n8k8.row.col.f32.tf32.tf32.f32 " \
        "{%0,%1,%2,%3}, {%4,%5,%6,%7}, {%8,%9}, {%0,%1,%2,%3};" \
        : "+f"(c0), "+f"(c1), "+f"(c2), "+f"(c3) \
        : "r"(a0), "r"(a1), "r"(a2), "r"(a3), "r"(b0), "r"(b1))

__device__ __forceinline__ void h8_to_f8(uint4 raw, float* f) {
    float2 p;
    p = __half22float2(*reinterpret_cast<__half2*>(&raw.x)); f[0] = p.x; f[1] = p.y;
    p = __half22float2(*reinterpret_cast<__half2*>(&raw.y)); f[2] = p.x; f[3] = p.y;
    p = __half22float2(*reinterpret_cast<__half2*>(&raw.z)); f[4] = p.x; f[5] = p.y;
    p = __half22float2(*reinterpret_cast<__half2*>(&raw.w)); f[6] = p.x; f[7] = p.y;
}

// ---------------- preprocessing ----------------
// convert x -> fp16, zero degree counters, zero scan flags
__global__ void k_convzero(const float* __restrict__ x) {
    int i = blockIdx.x * blockDim.x + threadIdx.x;   // [0, NN*8)
    if (i < NN * 8) {
        const float4* xp = reinterpret_cast<const float4*>(x) + (size_t)i * 2;
        float4 a = xp[0], b = xp[1];
        uint4 o;
        *reinterpret_cast<__half2*>(&o.x) = __floats2half2_rn(a.x, a.y);
        *reinterpret_cast<__half2*>(&o.y) = __floats2half2_rn(a.z, a.w);
        *reinterpret_cast<__half2*>(&o.z) = __floats2half2_rn(b.x, b.y);
        *reinterpret_cast<__half2*>(&o.w) = __floats2half2_rn(b.z, b.w);
        reinterpret_cast<uint4*>(g_x16)[i] = o;
    }
    if (i < NN) { g_outdeg[i] = 0; g_indeg[i] = 0; }
    if (i < SCAN_BLK) g_flag[i] = 0;
}

__global__ void k_degree(const int* __restrict__ src, const int* __restrict__ dst) {
    int e = blockIdx.x * blockDim.x + threadIdx.x;
    if (e < EE) {
        atomicAdd(&g_outdeg[src[e]], 1);
        atomicAdd(&g_indeg[dst[e]], 1);
    }
}

// single-pass scan (decoupled lookback over 49 co-resident blocks) + norms + cursor init
__global__ void k_scan() {
    __shared__ int sh[1024];
    __shared__ int off;
    int t = threadIdx.x;
    int bid = blockIdx.x;
    int i = bid * 1024 + t;

    int deg = (i < NN) ? g_indeg[i] : 0;
    if (i < NN) {
        g_norm_dst[i] = rsqrtf((float)max(deg, 1));
        g_norm_src[i] = rsqrtf((float)max(g_outdeg[i], 1));
    }
    sh[t] = deg;
    __syncthreads();
    #pragma unroll
    for (int o = 1; o < 1024; o <<= 1) {
        int x = (t >= o) ? sh[t - o] : 0;
        __syncthreads();
        sh[t] += x;
        __syncthreads();
    }
    if (t == 1023) {
        g_bsum[bid] = sh[1023];
        __threadfence();
        ((volatile int*)g_flag)[bid] = 1;
    }
    // exclusive offset over predecessor blocks (lookback; all 49 blocks resident)
    if (t < 32) {
        int s = 0;
        for (int b = t; b < bid; b += 32) {
            while (((volatile int*)g_flag)[b] == 0) {}
            s += ((volatile int*)g_bsum)[b];
        }
        #pragma unroll
        for (int o = 16; o > 0; o >>= 1) s += __shfl_down_sync(0xFFFFFFFFu, s, o);
        if (t == 0) off = s;
    }
    __syncthreads();
    if (i < NN) {
        int v = sh[t] + off;
        g_rowptr[i + 1] = v;
        if (i + 1 < NN) g_cursor[i + 1] = v;
        if (i == 0) { g_rowptr[0] = 0; g_cursor[0] = 0; }
    }
}

__global__ void k_scatter(const int* __restrict__ src, const int* __restrict__ dst) {
    int e = blockIdx.x * blockDim.x + threadIdx.x;
    if (e < EE) {
        int pos = atomicAdd(&g_cursor[dst[e]], 1);
        g_esrc[pos] = src[e];
    }
}

// ---------------- aggregation: one warp per node, 8 edge slots x 4 lanes x 32B ----------------
// LAYER1: feat = g_x16, scale by norm_src[u], out -> g_agg1 (fp16)
// !LAYER1: feat = g_h2,  epilogue acc*norm_dst + bias -> out_arg (fp32)
template <bool LAYER1>
__global__ void __launch_bounds__(256) k_agg(const float* __restrict__ bias,
                                             float* __restrict__ out_arg) {
    const uint4* __restrict__ feat = LAYER1
        ? reinterpret_cast<const uint4*>(g_x16)
        : reinterpret_cast<const uint4*>(g_h2);
    int n = blockIdx.x * 8 + (threadIdx.x >> 5);   // grid*8 == NN
    int lane = threadIdx.x & 31;
    int slot = lane >> 2;        // 8 slots (8 edges in flight)
    int fl   = lane & 3;         // 4 lanes/slot, 2 uint4 (16 halves) each

    int s = g_rowptr[n], e = g_rowptr[n + 1];
    float acc[16];
    #pragma unroll
    for (int k = 0; k < 16; k++) acc[k] = 0.f;

    #pragma unroll 2
    for (int j = s + slot; j < e; j += 8) {
        int u = g_esrc[j];
        uint4 r0 = feat[(size_t)u * 8 + fl * 2];
        uint4 r1 = feat[(size_t)u * 8 + fl * 2 + 1];
        float f[16];
        h8_to_f8(r0, f);
        h8_to_f8(r1, f + 8);
        if (LAYER1) {
            float sc = g_norm_src[u];
            #pragma unroll
            for (int k = 0; k < 16; k++) acc[k] = fmaf(f[k], sc, acc[k]);
        } else {
            #pragma unroll
            for (int k = 0; k < 16; k++) acc[k] += f[k];
        }
    }
    // combine 8 slots (offsets 16, 8, 4 keep fl alignment)
    #pragma unroll
    for (int o = 16; o >= 4; o >>= 1)
        #pragma unroll
        for (int k = 0; k < 16; k++)
            acc[k] += __shfl_down_sync(0xFFFFFFFFu, acc[k], o);

    if (slot == 0) {   // lanes 0..3: features [fl*16, fl*16+16)
        if (LAYER1) {
            uint4 o0, o1;
            *reinterpret_cast<__half2*>(&o0.x) = __floats2half2_rn(acc[0], acc[1]);
            *reinterpret_cast<__half2*>(&o0.y) = __floats2half2_rn(acc[2], acc[3]);
            *reinterpret_cast<__half2*>(&o0.z) = __floats2half2_rn(acc[4], acc[5]);
            *reinterpret_cast<__half2*>(&o0.w) = __floats2half2_rn(acc[6], acc[7]);
            *reinterpret_cast<__half2*>(&o1.x) = __floats2half2_rn(acc[8], acc[9]);
            *reinterpret_cast<__half2*>(&o1.y) = __floats2half2_rn(acc[10], acc[11]);
            *reinterpret_cast<__half2*>(&o1.z) = __floats2half2_rn(acc[12], acc[13]);
            *reinterpret_cast<__half2*>(&o1.w) = __floats2half2_rn(acc[14], acc[15]);
            reinterpret_cast<uint4*>(g_agg1)[(size_t)n * 8 + fl * 2]     = o0;
            reinterpret_cast<uint4*>(g_agg1)[(size_t)n * 8 + fl * 2 + 1] = o1;
        } else {
            float nd = g_norm_dst[n];
            float* op = out_arg + (size_t)n * 64 + fl * 16;
            const float4* bp = reinterpret_cast<const float4*>(bias) + fl * 4;
            #pragma unroll
            for (int q = 0; q < 4; q++) {
                float4 bv = bp[q];
                *reinterpret_cast<float4*>(op + q * 4) = make_float4(
                    fmaf(acc[q * 4 + 0], nd, bv.x), fmaf(acc[q * 4 + 1], nd, bv.y),
                    fmaf(acc[q * 4 + 2], nd, bv.z), fmaf(acc[q * 4 + 3], nd, bv.w));
            }
        }
    }
}

// ---------------- GEMM 1 (tf32 mma.sync): h1 = relu((agg1 @ W1)*nd + b1) ----------------
#define G1_AS_STRIDE 76
#define G1_WS_STRIDE 132
#define G1_WS_OFF  (128 * G1_AS_STRIDE)
#define G1_B1_OFF  (G1_WS_OFF + 64 * G1_WS_STRIDE)
#define G1_SMEM    ((G1_B1_OFF + 128) * 4)

__global__ void __launch_bounds__(256) k_gemm1_mma(const float* __restrict__ W1,
                                                   const float* __restrict__ b1) {
    extern __shared__ float sm[];
    float* As  = sm;
    float* Ws  = sm + G1_WS_OFF;
    float* sb1 = sm + G1_B1_OFF;

    int tid = threadIdx.x;
    int row0 = blockIdx.x * 128;

    #pragma unroll
    for (int it = 0; it < 4; it++) {
        int idx = tid + it * 256;
        int r = idx >> 3, c8 = idx & 7;
        int row = row0 + r;
        float f[8] = {0.f, 0.f, 0.f, 0.f, 0.f, 0.f, 0.f, 0.f};
        if (row < NN) {
            uint4 raw = reinterpret_cast<const uint4*>(g_agg1)[(size_t)row * 8 + c8];
            h8_to_f8(raw, f);
        }
        float* p = &As[r * G1_AS_STRIDE + c8 * 8];
        #pragma unroll
        for (int k = 0; k < 8; k++) p[k] = __uint_as_float(f2tf32(f[k]));
    }
    #pragma unroll
    for (int it = 0; it < 8; it++) {
        int idx4 = tid + it * 256;
        int k = idx4 >> 5, c4 = idx4 & 31;
        float4 v = *reinterpret_cast<const float4*>(&W1[(size_t)k * 128 + c4 * 4]);
        float* p = &Ws[k * G1_WS_STRIDE + c4 * 4];
        p[0] = __uint_as_float(f2tf32(v.x)); p[1] = __uint_as_float(f2tf32(v.y));
        p[2] = __uint_as_float(f2tf32(v.z)); p[3] = __uint_as_float(f2tf32(v.w));
    }
    if (tid < 128) sb1[tid] = b1[tid];
    __syncthreads();

    int w = tid >> 5, lane = tid & 31;
    int wr = w >> 1, wc = w & 1;
    int g = lane >> 2, t4 = lane & 3;

    float c[2][8][4];
    #pragma unroll
    for (int i = 0; i < 2; i++)
        #pragma unroll
        for (int j = 0; j < 8; j++)
            #pragma unroll
            for (int q = 0; q < 4; q++) c[i][j][q] = 0.f;

    const uint32_t* Au = reinterpret_cast<const uint32_t*>(As);
    const uint32_t* Wu = reinterpret_cast<const uint32_t*>(Ws);

    #pragma unroll
    for (int ks = 0; ks < 8; ks++) {
        int kb = ks * 8;
        uint32_t a[2][4];
        #pragma unroll
        for (int rf = 0; rf < 2; rf++) {
            int R = wr * 32 + rf * 16;
            a[rf][0] = Au[(R + g) * G1_AS_STRIDE + kb + t4];
            a[rf][1] = Au[(R + 8 + g) * G1_AS_STRIDE + kb + t4];
            a[rf][2] = Au[(R + g) * G1_AS_STRIDE + kb + 4 + t4];
            a[rf][3] = Au[(R + 8 + g) * G1_AS_STRIDE + kb + 4 + t4];
        }
        #pragma unroll
        for (int cf = 0; cf < 8; cf++) {
            int C = wc * 64 + cf * 8 + g;
            uint32_t b0 = Wu[(kb + t4) * G1_WS_STRIDE + C];
            uint32_t b1r = Wu[(kb + 4 + t4) * G1_WS_STRIDE + C];
            #pragma unroll
            for (int rf = 0; rf < 2; rf++)
                MMA_TF32(c[rf][cf][0], c[rf][cf][1], c[rf][cf][2], c[rf][cf][3],
                         a[rf][0], a[rf][1], a[rf][2], a[rf][3], b0, b1r);
        }
    }

    #pragma unroll
    for (int rf = 0; rf < 2; rf++) {
        int r1 = row0 + wr * 32 + rf * 16 + g;
        int r2 = r1 + 8;
        float nd1 = (r1 < NN) ? g_norm_dst[r1] : 0.f;
        float nd2 = (r2 < NN) ? g_norm_dst[r2] : 0.f;
        #pragma unroll
        for (int cf = 0; cf < 8; cf++) {
            int col = wc * 64 + cf * 8 + 2 * t4;
            float bx = sb1[col], by = sb1[col + 1];
            if (r1 < NN)
                *reinterpret_cast<__half2*>(&g_h1[(size_t)r1 * 128 + col]) =
                    __floats2half2_rn(fmaxf(fmaf(c[rf][cf][0], nd1, bx), 0.f),
                                      fmaxf(fmaf(c[rf][cf][1], nd1, by), 0.f));
            if (r2 < NN)
                *reinterpret_cast<__half2*>(&g_h1[(size_t)r2 * 128 + col]) =
                    __floats2half2_rn(fmaxf(fmaf(c[rf][cf][2], nd2, bx), 0.f),
                                      fmaxf(fmaf(c[rf][cf][3], nd2, by), 0.f));
        }
    }
}

// ---------------- GEMM 2 (tf32 mma.sync): h2 = (h1 * norm_src) @ W2 ----------------
#define G2_AS_STRIDE 132
#define G2_WS_STRIDE 68
#define G2_WS_OFF  (128 * G2_AS_STRIDE)
#define G2_NS_OFF  (G2_WS_OFF + 128 * G2_WS_STRIDE)
#define G2_SMEM    ((G2_NS_OFF + 128) * 4)

__global__ void __launch_bounds__(256) k_gemm2_mma(const float* __restrict__ W2) {
    extern __shared__ float sm[];
    float* As  = sm;
    float* Ws  = sm + G2_WS_OFF;
    float* sns = sm + G2_NS_OFF;

    int tid = threadIdx.x;
    int row0 = blockIdx.x * 128;

    if (tid < 128) {
        int row = row0 + tid;
        sns[tid] = (row < NN) ? g_norm_src[row] : 0.f;
    }
    __syncthreads();

    #pragma unroll
    for (int it = 0; it < 8; it++) {
        int idx = tid + it * 256;
        int r = idx >> 4, c8 = idx & 15;
        int row = row0 + r;
        float f[8] = {0.f, 0.f, 0.f, 0.f, 0.f, 0.f, 0.f, 0.f};
        if (row < NN) {
            uint4 raw = reinterpret_cast<const uint4*>(g_h1)[(size_t)row * 16 + c8];
            h8_to_f8(raw, f);
        }
        float s = sns[r];
        float* p = &As[r * G2_AS_STRIDE + c8 * 8];
        #pragma unroll
        for (int k = 0; k < 8; k++) p[k] = __uint_as_float(f2tf32(f[k] * s));
    }
    #pragma unroll
    for (int it = 0; it < 8; it++) {
        int idx4 = tid + it * 256;
        int k = idx4 >> 4, c4 = idx4 & 15;
        float4 v = *reinterpret_cast<const float4*>(&W2[(size_t)k * 64 + c4 * 4]);
        float* p = &Ws[k * G2_WS_STRIDE + c4 * 4];
        p[0] = __uint_as_float(f2tf32(v.x)); p[1] = __uint_as_float(f2tf32(v.y));
        p[2] = __uint_as_float(f2tf32(v.z)); p[3] = __uint_as_float(f2tf32(v.w));
    }
    __syncthreads();

    int w = tid >> 5, lane = tid & 31;
    int wr = w >> 1, wc = w & 1;
    int g = lane >> 2, t4 = lane & 3;

    float c[2][4][4];
    #pragma unroll
    for (int i = 0; i < 2; i++)
        #pragma unroll
        for (int j = 0; j < 4; j++)
            #pragma unroll
            for (int q = 0; q < 4; q++) c[i][j][q] = 0.f;

    const uint32_t* Au = reinterpret_cast<const uint32_t*>(As);
    const uint32_t* Wu = reinterpret_cast<const uint32_t*>(Ws);

    #pragma unroll
    for (int ks = 0; ks < 16; ks++) {
        int kb = ks * 8;
        uint32_t a[2][4];
        #pragma unroll
        for (int rf = 0; rf < 2; rf++) {
            int R = wr * 32 + rf * 16;
            a[rf][0] = Au[(R + g) * G2_AS_STRIDE + kb + t4];
            a[rf][1] = Au[(R + 8 + g) * G2_AS_STRIDE + kb + t4];
            a[rf][2] = Au[(R + g) * G2_AS_STRIDE + kb + 4 + t4];
            a[rf][3] = Au[(R + 8 + g) * G2_AS_STRIDE + kb + 4 + t4];
        }
        #pragma unroll
        for (int cf = 0; cf < 4; cf++) {
            int C = wc * 32 + cf * 8 + g;
            uint32_t b0 = Wu[(kb + t4) * G2_WS_STRIDE + C];
            uint32_t b1r = Wu[(kb + 4 + t4) * G2_WS_STRIDE + C];
            #pragma unroll
            for (int rf = 0; rf < 2; rf++)
                MMA_TF32(c[rf][cf][0], c[rf][cf][1], c[rf][cf][2], c[rf][cf][3],
                         a[rf][0], a[rf][1], a[rf][2], a[rf][3], b0, b1r);
        }
    }

    #pragma unroll
    for (int rf = 0; rf < 2; rf++) {
        int r1 = row0 + wr * 32 + rf * 16 + g;
        int r2 = r1 + 8;
        #pragma unroll
        for (int cf = 0; cf < 4; cf++) {
            int col = wc * 32 + cf * 8 + 2 * t4;
            if (r1 < NN)
                *reinterpret_cast<__half2*>(&g_h2[(size_t)r1 * 64 + col]) =
                    __floats2half2_rn(c[rf][cf][0], c[rf][cf][1]);
            if (r2 < NN)
                *reinterpret_cast<__half2*>(&g_h2[(size_t)r2 * 64 + col]) =
                    __floats2half2_rn(c[rf][cf][2], c[rf][cf][3]);
        }
    }
}

// ---------------- launch ----------------
extern "C" void kernel_launch(void* const* d_in, const int* in_sizes, int n_in,
                              void* d_out, int out_size) {
    const float* x   = (const float*)d_in[0];
    const float* W1  = (const float*)d_in[1];
    const float* b1  = (const float*)d_in[2];
    const float* W2  = (const float*)d_in[3];
    const float* b2  = (const float*)d_in[4];
    const int*   src = (const int*)d_in[5];
    const int*   dst = (const int*)d_in[6];
    float* out = (float*)d_out;

    cudaFuncSetAttribute(k_gemm1_mma, cudaFuncAttributeMaxDynamicSharedMemorySize, G1_SMEM);
    cudaFuncSetAttribute(k_gemm2_mma, cudaFuncAttributeMaxDynamicSharedMemorySize, G2_SMEM);

    k_convzero<<<(NN * 8 + 255) / 256, 256>>>(x);
    k_degree<<<(EE + 255) / 256, 256>>>(src, dst);
    k_scan<<<SCAN_BLK, 1024>>>();
    k_scatter<<<(EE + 255) / 256, 256>>>(src, dst);

    int ntiles = (NN + 127) / 128;   // 391
    k_agg<true><<<NN / 8, 256>>>(nullptr, nullptr);
    k_gemm1_mma<<<ntiles, 256, G1_SMEM>>>(W1, b1);
    k_gemm2_mma<<<ntiles, 256, G2_SMEM>>>(W2);
    k_agg<false><<<NN / 8, 256>>>(b2, out);
}

// round 11
// speedup vs baseline: 1.1402x; 1.1402x over previous
#include <cuda_runtime.h>
#include <cuda_fp16.h>
#include <cstdint>

#define NN 50000
#define EE 800000
#define SCAN_BLK ((NN + 1023) / 1024)   // 49

// ---------------- device scratch (no allocations allowed) ----------------
__device__ __align__(16) int    g_outdeg[NN];
__device__ __align__(16) int    g_indeg[NN];
__device__ __align__(16) int    g_cursor[NN];
__device__ __align__(16) int    g_rowptr[NN + 1];
__device__ __align__(16) int    g_esrc[EE];
__device__ __align__(16) int    g_bsum[SCAN_BLK];
__device__ __align__(16) float  g_norm_src[NN];
__device__ __align__(16) float  g_norm_dst[NN];
__device__ __align__(16) __half g_x16[(size_t)NN * 64];
__device__ __align__(16) __half g_agg1[(size_t)NN * 64];
__device__ __align__(16) __half g_h1[(size_t)NN * 128];
__device__ __align__(16) __half g_h2[(size_t)NN * 64];

__device__ __forceinline__ uint32_t f2tf32(float v) {
    uint32_t u;
    asm("cvt.rna.tf32.f32 %0, %1;" : "=r"(u) : "f"(v));
    return u;
}

#define MMA_TF32(c0, c1, c2, c3, a0, a1, a2, a3, b0, b1) \
    asm volatile("mma.sync.aligned.m16n8k8.row.col.f32.tf32.tf32.f32 " \
        "{%0,%1,%2,%3}, {%4,%5,%6,%7}, {%8,%9}, {%0,%1,%2,%3};" \
        : "+f"(c0), "+f"(c1), "+f"(c2), "+f"(c3) \
        : "r"(a0), "r"(a1), "r"(a2), "r"(a3), "r"(b0), "r"(b1))

__device__ __forceinline__ void h8_to_f8(uint4 raw, float* f) {
    float2 p;
    p = __half22float2(*reinterpret_cast<__half2*>(&raw.x)); f[0] = p.x; f[1] = p.y;
    p = __half22float2(*reinterpret_cast<__half2*>(&raw.y)); f[2] = p.x; f[3] = p.y;
    p = __half22float2(*reinterpret_cast<__half2*>(&raw.z)); f[4] = p.x; f[5] = p.y;
    p = __half22float2(*reinterpret_cast<__half2*>(&raw.w)); f[6] = p.x; f[7] = p.y;
}

// ---------------- preprocessing ----------------
__global__ void k_convzero(const float* __restrict__ x) {
    int i = blockIdx.x * blockDim.x + threadIdx.x;   // [0, NN*8)
    if (i < NN * 8) {
        const float4* xp = reinterpret_cast<const float4*>(x) + (size_t)i * 2;
        float4 a = xp[0], b = xp[1];
        uint4 o;
        *reinterpret_cast<__half2*>(&o.x) = __floats2half2_rn(a.x, a.y);
        *reinterpret_cast<__half2*>(&o.y) = __floats2half2_rn(a.z, a.w);
        *reinterpret_cast<__half2*>(&o.z) = __floats2half2_rn(b.x, b.y);
        *reinterpret_cast<__half2*>(&o.w) = __floats2half2_rn(b.z, b.w);
        reinterpret_cast<uint4*>(g_x16)[i] = o;
    }
    if (i < NN) { g_outdeg[i] = 0; g_indeg[i] = 0; }
}

// 4 edges per thread: independent atomic chains, coalesced int4 edge reads
__global__ void k_degree(const int* __restrict__ src, const int* __restrict__ dst) {
    int i = blockIdx.x * blockDim.x + threadIdx.x;   // [0, EE/4)
    if (i < EE / 4) {
        int4 s4 = reinterpret_cast<const int4*>(src)[i];
        int4 d4 = reinterpret_cast<const int4*>(dst)[i];
        atomicAdd(&g_outdeg[s4.x], 1); atomicAdd(&g_outdeg[s4.y], 1);
        atomicAdd(&g_outdeg[s4.z], 1); atomicAdd(&g_outdeg[s4.w], 1);
        atomicAdd(&g_indeg[d4.x], 1);  atomicAdd(&g_indeg[d4.y], 1);
        atomicAdd(&g_indeg[d4.z], 1);  atomicAdd(&g_indeg[d4.w], 1);
    }
}

// per-block inclusive scan of indeg; norms fused (R9-proven)
__global__ void k_scan_blk() {
    __shared__ int sh[1024];
    int t = threadIdx.x;
    int i = blockIdx.x * 1024 + t;
    int deg = (i < NN) ? g_indeg[i] : 0;
    if (i < NN) {
        g_norm_dst[i] = rsqrtf((float)max(deg, 1));
        g_norm_src[i] = rsqrtf((float)max(g_outdeg[i], 1));
    }
    sh[t] = deg;
    __syncthreads();
    #pragma unroll
    for (int off = 1; off < 1024; off <<= 1) {
        int x = (t >= off) ? sh[t - off] : 0;
        __syncthreads();
        sh[t] += x;
        __syncthreads();
    }
    if (i < NN) g_rowptr[i + 1] = sh[t];
    if (t == 1023) g_bsum[blockIdx.x] = sh[1023];
}

__global__ void k_scan_add() {
    __shared__ int off;
    int t = threadIdx.x;
    int i = blockIdx.x * 1024 + t;
    if (t < 32) {
        int s = 0;
        for (int b = t; b < blockIdx.x; b += 32) s += g_bsum[b];
        #pragma unroll
        for (int o = 16; o > 0; o >>= 1) s += __shfl_down_sync(0xFFFFFFFFu, s, o);
        if (t == 0) off = s;
    }
    __syncthreads();
    if (i < NN) {
        int v = g_rowptr[i + 1] + off;
        g_rowptr[i + 1] = v;
        if (i + 1 < NN) g_cursor[i + 1] = v;
        if (i == 0) { g_rowptr[0] = 0; g_cursor[0] = 0; }
    }
}

// 4 edges per thread (same MLP rationale as k_degree)
__global__ void k_scatter(const int* __restrict__ src, const int* __restrict__ dst) {
    int i = blockIdx.x * blockDim.x + threadIdx.x;   // [0, EE/4)
    if (i < EE / 4) {
        int4 s4 = reinterpret_cast<const int4*>(src)[i];
        int4 d4 = reinterpret_cast<const int4*>(dst)[i];
        int p0 = atomicAdd(&g_cursor[d4.x], 1);
        int p1 = atomicAdd(&g_cursor[d4.y], 1);
        int p2 = atomicAdd(&g_cursor[d4.z], 1);
        int p3 = atomicAdd(&g_cursor[d4.w], 1);
        g_esrc[p0] = s4.x; g_esrc[p1] = s4.y;
        g_esrc[p2] = s4.z; g_esrc[p3] = s4.w;
    }
}

// ---------------- aggregation: one warp per node, 4 edge slots x 8 lanes x 16B (R9) ----------------
template <bool LAYER1>
__global__ void __launch_bounds__(256) k_agg(const float* __restrict__ bias,
                                             float* __restrict__ out_arg) {
    const uint4* __restrict__ feat = LAYER1
        ? reinterpret_cast<const uint4*>(g_x16)
        : reinterpret_cast<const uint4*>(g_h2);
    int n = blockIdx.x * 8 + (threadIdx.x >> 5);   // grid*8 == NN
    int lane = threadIdx.x & 31;
    int slot = lane >> 3;        // 4 slots
    int fl   = lane & 7;         // 8 lanes/slot, 8 halves each

    int s = g_rowptr[n], e = g_rowptr[n + 1];
    float acc[8] = {0.f, 0.f, 0.f, 0.f, 0.f, 0.f, 0.f, 0.f};
    #pragma unroll 2
    for (int j = s + slot; j < e; j += 4) {
        int u = g_esrc[j];
        uint4 raw = feat[(size_t)u * 8 + fl];
        float f[8];
        h8_to_f8(raw, f);
        if (LAYER1) {
            float sc = g_norm_src[u];
            #pragma unroll
            for (int k = 0; k < 8; k++) acc[k] = fmaf(f[k], sc, acc[k]);
        } else {
            #pragma unroll
            for (int k = 0; k < 8; k++) acc[k] += f[k];
        }
    }
    #pragma unroll
    for (int o = 16; o >= 8; o >>= 1)
        #pragma unroll
        for (int k = 0; k < 8; k++)
            acc[k] += __shfl_down_sync(0xFFFFFFFFu, acc[k], o);

    if (slot == 0) {
        if (LAYER1) {
            uint4 o;
            *reinterpret_cast<__half2*>(&o.x) = __floats2half2_rn(acc[0], acc[1]);
            *reinterpret_cast<__half2*>(&o.y) = __floats2half2_rn(acc[2], acc[3]);
            *reinterpret_cast<__half2*>(&o.z) = __floats2half2_rn(acc[4], acc[5]);
            *reinterpret_cast<__half2*>(&o.w) = __floats2half2_rn(acc[6], acc[7]);
            reinterpret_cast<uint4*>(g_agg1)[(size_t)n * 8 + fl] = o;
        } else {
            float nd = g_norm_dst[n];
            float4 b0 = reinterpret_cast<const float4*>(bias)[fl * 2];
            float4 b1 = reinterpret_cast<const float4*>(bias)[fl * 2 + 1];
            float* op = out_arg + (size_t)n * 64 + fl * 8;
            *reinterpret_cast<float4*>(op) = make_float4(
                fmaf(acc[0], nd, b0.x), fmaf(acc[1], nd, b0.y),
                fmaf(acc[2], nd, b0.z), fmaf(acc[3], nd, b0.w));
            *reinterpret_cast<float4*>(op + 4) = make_float4(
                fmaf(acc[4], nd, b1.x), fmaf(acc[5], nd, b1.y),
                fmaf(acc[6], nd, b1.z), fmaf(acc[7], nd, b1.w));
        }
    }
}

// ---------------- GEMM 1 (tf32 mma.sync): h1 = relu((agg1 @ W1)*nd + b1) ----------------
#define G1_AS_STRIDE 76
#define G1_WS_STRIDE 132
#define G1_WS_OFF  (128 * G1_AS_STRIDE)
#define G1_B1_OFF  (G1_WS_OFF + 64 * G1_WS_STRIDE)
#define G1_SMEM    ((G1_B1_OFF + 128) * 4)

__global__ void __launch_bounds__(256) k_gemm1_mma(const float* __restrict__ W1,
                                                   const float* __restrict__ b1) {
    extern __shared__ float sm[];
    float* As  = sm;
    float* Ws  = sm + G1_WS_OFF;
    float* sb1 = sm + G1_B1_OFF;

    int tid = threadIdx.x;
    int row0 = blockIdx.x * 128;

    #pragma unroll
    for (int it = 0; it < 4; it++) {
        int idx = tid + it * 256;
        int r = idx >> 3, c8 = idx & 7;
        int row = row0 + r;
        float f[8] = {0.f, 0.f, 0.f, 0.f, 0.f, 0.f, 0.f, 0.f};
        if (row < NN) {
            uint4 raw = reinterpret_cast<const uint4*>(g_agg1)[(size_t)row * 8 + c8];
            h8_to_f8(raw, f);
        }
        float* p = &As[r * G1_AS_STRIDE + c8 * 8];
        #pragma unroll
        for (int k = 0; k < 8; k++) p[k] = __uint_as_float(f2tf32(f[k]));
    }
    #pragma unroll
    for (int it = 0; it < 8; it++) {
        int idx4 = tid + it * 256;
        int k = idx4 >> 5, c4 = idx4 & 31;
        float4 v = *reinterpret_cast<const float4*>(&W1[(size_t)k * 128 + c4 * 4]);
        float* p = &Ws[k * G1_WS_STRIDE + c4 * 4];
        p[0] = __uint_as_float(f2tf32(v.x)); p[1] = __uint_as_float(f2tf32(v.y));
        p[2] = __uint_as_float(f2tf32(v.z)); p[3] = __uint_as_float(f2tf32(v.w));
    }
    if (tid < 128) sb1[tid] = b1[tid];
    __syncthreads();

    int w = tid >> 5, lane = tid & 31;
    int wr = w >> 1, wc = w & 1;
    int g = lane >> 2, t4 = lane & 3;

    float c[2][8][4];
    #pragma unroll
    for (int i = 0; i < 2; i++)
        #pragma unroll
        for (int j = 0; j < 8; j++)
            #pragma unroll
            for (int q = 0; q < 4; q++) c[i][j][q] = 0.f;

    const uint32_t* Au = reinterpret_cast<const uint32_t*>(As);
    const uint32_t* Wu = reinterpret_cast<const uint32_t*>(Ws);

    #pragma unroll
    for (int ks = 0; ks < 8; ks++) {
        int kb = ks * 8;
        uint32_t a[2][4];
        #pragma unroll
        for (int rf = 0; rf < 2; rf++) {
            int R = wr * 32 + rf * 16;
            a[rf][0] = Au[(R + g) * G1_AS_STRIDE + kb + t4];
            a[rf][1] = Au[(R + 8 + g) * G1_AS_STRIDE + kb + t4];
            a[rf][2] = Au[(R + g) * G1_AS_STRIDE + kb + 4 + t4];
            a[rf][3] = Au[(R + 8 + g) * G1_AS_STRIDE + kb + 4 + t4];
        }
        #pragma unroll
        for (int cf = 0; cf < 8; cf++) {
            int C = wc * 64 + cf * 8 + g;
            uint32_t b0 = Wu[(kb + t4) * G1_WS_STRIDE + C];
            uint32_t b1r = Wu[(kb + 4 + t4) * G1_WS_STRIDE + C];
            #pragma unroll
            for (int rf = 0; rf < 2; rf++)
                MMA_TF32(c[rf][cf][0], c[rf][cf][1], c[rf][cf][2], c[rf][cf][3],
                         a[rf][0], a[rf][1], a[rf][2], a[rf][3], b0, b1r);
        }
    }

    #pragma unroll
    for (int rf = 0; rf < 2; rf++) {
        int r1 = row0 + wr * 32 + rf * 16 + g;
        int r2 = r1 + 8;
        float nd1 = (r1 < NN) ? g_norm_dst[r1] : 0.f;
        float nd2 = (r2 < NN) ? g_norm_dst[r2] : 0.f;
        #pragma unroll
        for (int cf = 0; cf < 8; cf++) {
            int col = wc * 64 + cf * 8 + 2 * t4;
            float bx = sb1[col], by = sb1[col + 1];
            if (r1 < NN)
                *reinterpret_cast<__half2*>(&g_h1[(size_t)r1 * 128 + col]) =
                    __floats2half2_rn(fmaxf(fmaf(c[rf][cf][0], nd1, bx), 0.f),
                                      fmaxf(fmaf(c[rf][cf][1], nd1, by), 0.f));
            if (r2 < NN)
                *reinterpret_cast<__half2*>(&g_h1[(size_t)r2 * 128 + col]) =
                    __floats2half2_rn(fmaxf(fmaf(c[rf][cf][2], nd2, bx), 0.f),
                                      fmaxf(fmaf(c[rf][cf][3], nd2, by), 0.f));
        }
    }
}

// ---------------- GEMM 2 (tf32 mma.sync): h2 = (h1 * norm_src) @ W2 ----------------
#define G2_AS_STRIDE 132
#define G2_WS_STRIDE 68
#define G2_WS_OFF  (128 * G2_AS_STRIDE)
#define G2_NS_OFF  (G2_WS_OFF + 128 * G2_WS_STRIDE)
#define G2_SMEM    ((G2_NS_OFF + 128) * 4)

__global__ void __launch_bounds__(256) k_gemm2_mma(const float* __restrict__ W2) {
    extern __shared__ float sm[];
    float* As  = sm;
    float* Ws  = sm + G2_WS_OFF;
    float* sns = sm + G2_NS_OFF;

    int tid = threadIdx.x;
    int row0 = blockIdx.x * 128;

    if (tid < 128) {
        int row = row0 + tid;
        sns[tid] = (row < NN) ? g_norm_src[row] : 0.f;
    }
    __syncthreads();

    #pragma unroll
    for (int it = 0; it < 8; it++) {
        int idx = tid + it * 256;
        int r = idx >> 4, c8 = idx & 15;
        int row = row0 + r;
        float f[8] = {0.f, 0.f, 0.f, 0.f, 0.f, 0.f, 0.f, 0.f};
        if (row < NN) {
            uint4 raw = reinterpret_cast<const uint4*>(g_h1)[(size_t)row * 16 + c8];
            h8_to_f8(raw, f);
        }
        float s = sns[r];
        float* p = &As[r * G2_AS_STRIDE + c8 * 8];
        #pragma unroll
        for (int k = 0; k < 8; k++) p[k] = __uint_as_float(f2tf32(f[k] * s));
    }
    #pragma unroll
    for (int it = 0; it < 8; it++) {
        int idx4 = tid + it * 256;
        int k = idx4 >> 4, c4 = idx4 & 15;
        float4 v = *reinterpret_cast<const float4*>(&W2[(size_t)k * 64 + c4 * 4]);
        float* p = &Ws[k * G2_WS_STRIDE + c4 * 4];
        p[0] = __uint_as_float(f2tf32(v.x)); p[1] = __uint_as_float(f2tf32(v.y));
        p[2] = __uint_as_float(f2tf32(v.z)); p[3] = __uint_as_float(f2tf32(v.w));
    }
    __syncthreads();

    int w = tid >> 5, lane = tid & 31;
    int wr = w >> 1, wc = w & 1;
    int g = lane >> 2, t4 = lane & 3;

    float c[2][4][4];
    #pragma unroll
    for (int i = 0; i < 2; i++)
        #pragma unroll
        for (int j = 0; j < 4; j++)
            #pragma unroll
            for (int q = 0; q < 4; q++) c[i][j][q] = 0.f;

    const uint32_t* Au = reinterpret_cast<const uint32_t*>(As);
    const uint32_t* Wu = reinterpret_cast<const uint32_t*>(Ws);

    #pragma unroll
    for (int ks = 0; ks < 16; ks++) {
        int kb = ks * 8;
        uint32_t a[2][4];
        #pragma unroll
        for (int rf = 0; rf < 2; rf++) {
            int R = wr * 32 + rf * 16;
            a[rf][0] = Au[(R + g) * G2_AS_STRIDE + kb + t4];
            a[rf][1] = Au[(R + 8 + g) * G2_AS_STRIDE + kb + t4];
            a[rf][2] = Au[(R + g) * G2_AS_STRIDE + kb + 4 + t4];
            a[rf][3] = Au[(R + 8 + g) * G2_AS_STRIDE + kb + 4 + t4];
        }
        #pragma unroll
        for (int cf = 0; cf < 4; cf++) {
            int C = wc * 32 + cf * 8 + g;
            uint32_t b0 = Wu[(kb + t4) * G2_WS_STRIDE + C];
            uint32_t b1r = Wu[(kb + 4 + t4) * G2_WS_STRIDE + C];
            #pragma unroll
            for (int rf = 0; rf < 2; rf++)
                MMA_TF32(c[rf][cf][0], c[rf][cf][1], c[rf][cf][2], c[rf][cf][3],
                         a[rf][0], a[rf][1], a[rf][2], a[rf][3], b0, b1r);
        }
    }

    #pragma unroll
    for (int rf = 0; rf < 2; rf++) {
        int r1 = row0 + wr * 32 + rf * 16 + g;
        int r2 = r1 + 8;
        #pragma unroll
        for (int cf = 0; cf < 4; cf++) {
            int col = wc * 32 + cf * 8 + 2 * t4;
            if (r1 < NN)
                *reinterpret_cast<__half2*>(&g_h2[(size_t)r1 * 64 + col]) =
                    __floats2half2_rn(c[rf][cf][0], c[rf][cf][1]);
            if (r2 < NN)
                *reinterpret_cast<__half2*>(&g_h2[(size_t)r2 * 64 + col]) =
                    __floats2half2_rn(c[rf][cf][2], c[rf][cf][3]);
        }
    }
}

// ---------------- launch ----------------
extern "C" void kernel_launch(void* const* d_in, const int* in_sizes, int n_in,
                              void* d_out, int out_size) {
    const float* x   = (const float*)d_in[0];
    const float* W1  = (const float*)d_in[1];
    const float* b1  = (const float*)d_in[2];
    const float* W2  = (const float*)d_in[3];
    const float* b2  = (const float*)d_in[4];
    const int*   src = (const int*)d_in[5];
    const int*   dst = (const int*)d_in[6];
    float* out = (float*)d_out;

    cudaFuncSetAttribute(k_gemm1_mma, cudaFuncAttributeMaxDynamicSharedMemorySize, G1_SMEM);
    cudaFuncSetAttribute(k_gemm2_mma, cudaFuncAttributeMaxDynamicSharedMemorySize, G2_SMEM);

    k_convzero<<<(NN * 8 + 255) / 256, 256>>>(x);
    k_degree<<<(EE / 4 + 255) / 256, 256>>>(src, dst);
    k_scan_blk<<<SCAN_BLK, 1024>>>();
    k_scan_add<<<SCAN_BLK, 1024>>>();
    k_scatter<<<(EE / 4 + 255) / 256, 256>>>(src, dst);

    int ntiles = (NN + 127) / 128;   // 391
    k_agg<true><<<NN / 8, 256>>>(nullptr, nullptr);
    k_gemm1_mma<<<ntiles, 256, G1_SMEM>>>(W1, b1);
    k_gemm2_mma<<<ntiles, 256, G2_SMEM>>>(W2);
    k_agg<false><<<NN / 8, 256>>>(b2, out);
}